// round 6
// baseline (speedup 1.0000x reference)
#include <cuda_runtime.h>

// QuantumLayer_9483287790225 — analytic closed form (R0 derivation).
//
//   z_i = cos(pi*x_i) * ( cos(w_i) - sin(w_i)*sin(pi*x_i) )
//   <Z_0> = z_1*...*z_13 ;  <Z_j> = z_0*...*z_j  (j>=1)
//
// R4: 8 lanes per batch, 2 wires per lane (float2, 56B row stride is
// 8B-aligned). Lane L: q_L = z_{2L}*z_{2L+1}, lane 0 drops z_0, lane 7
// pads 1. 3-step shfl product scan -> I_L = z_1..z_{2L+1}.
//   out[2L+1] = z0 * I_L                (valid for ALL lanes incl. 0)
//   out[2L]   = z0 * E_L * z_{2L}  (L>=1),  out[0] = I_7
// Kernel is launch-overhead-floor bound (~5000cyc T_ovh + cold load);
// body is ~400 cyc. This round trims the post-scan chain + spreads CTAs.

#define NQ 14
#define BATCH 256
#define PI_F 3.14159265358979323846f

__global__ void __launch_bounds__(64, 1)
quantum_layer_kernel(const float* __restrict__ x,
                     const float* __restrict__ weight,
                     float* __restrict__ out)
{
    const unsigned tid = blockIdx.x * blockDim.x + threadIdx.x;
    const unsigned sub = tid & 7u;          // lane within 8-lane batch group
    const unsigned b   = tid >> 3;          // batch index

    float2 xv = make_float2(0.0f, 0.0f);
    float2 wv = make_float2(0.0f, 0.0f);
    if (sub < 7u) {
        xv = *(const float2*)(x + b * NQ + 2 * sub);
        wv.x = __ldg(weight + 2 * sub);
        wv.y = __ldg(weight + 2 * sub + 1);
    }

    // z = cp * (cw - sw*sp); two independent wires give MUFU ILP.
    float aa = PI_F * xv.x, ab = PI_F * xv.y;
    float za = __cosf(aa) * (__cosf(wv.x) - __sinf(wv.x) * __sinf(aa));
    float zb = __cosf(ab) * (__cosf(wv.y) - __sinf(wv.y) * __sinf(ab));

    // Scan input: lane 0 excludes z_0; lane 7 contributes identity.
    float q = (sub == 0u) ? zb : za * zb;
    if (sub == 7u) q = 1.0f;

    // 3-step inclusive product scan over 8-lane groups.
    float I = q;
#pragma unroll
    for (int d = 1; d < 8; d <<= 1) {
        float t = __shfl_up_sync(0xffffffffu, I, d, 8);
        if (sub >= (unsigned)d) I *= t;
    }

    float E   = __shfl_up_sync(0xffffffffu, I, 1, 8);   // exclusive scan
    float z0  = __shfl_sync(0xffffffffu, za, 0, 8);     // z_0
    float s13 = __shfl_sync(0xffffffffu, I, 7, 8);      // z_1..z_13

    if (sub < 7u) {
        float o1 = z0 * I;                               // out[2L+1], all lanes
        float o0 = (sub == 0u) ? s13 : z0 * E * za;      // out[2L]
        *(float2*)(out + b * NQ + 2 * sub) = make_float2(o0, o1);
    }
}

extern "C" void kernel_launch(void* const* d_in, const int* in_sizes, int n_in,
                              void* d_out, int out_size)
{
    const float* x      = (const float*)d_in[0];   // [256, 14]
    const float* weight = (const float*)d_in[1];   // [1, 14]
    float* out          = (float*)d_out;           // [256, 14]

    // 2048 threads as 32 CTAs x 64 -> more SMs engaged, smaller tail.
    quantum_layer_kernel<<<32, 64>>>(x, weight, out);
}

// round 7
// speedup vs baseline: 1.2293x; 1.2293x over previous
#include <cuda_runtime.h>

// QuantumLayer_9483287790225 — analytic closed form (R0 derivation).
//
//   z_i = cos(pi*x_i) * ( cos(w_i) - sin(w_i)*sin(pi*x_i) )
//   <Z_0> = z_1*...*z_13 ;  <Z_j> = z_0*...*z_j  (j>=1)
//
// R6: revert to the measured-best launch shape (R2: 32 CTAs x 128 threads,
// 16 lanes per batch sample, lane = wire). Lane i computes z_i; a 4-step
// shfl_up product scan of v = (i==0 || i>=14 ? 1 : z_i) yields
// I_j = z_1..z_j. Outputs: out[0] = I_13, out[j] = z_0 * I_j.
// Kernel is launch-overhead-floor bound; R4's 32x64 shape regressed 1us,
// so only the branch-free padding + shortened post-scan chain are kept.

#define NQ 14
#define BATCH 256
#define PI_F 3.14159265358979323846f

__global__ void __launch_bounds__(128, 1)
quantum_layer_kernel(const float* __restrict__ x,
                     const float* __restrict__ weight,
                     float* __restrict__ out)
{
    const unsigned tid = blockIdx.x * blockDim.x + threadIdx.x;
    const unsigned sub = tid & 15u;          // wire index within 16-lane group
    const unsigned b   = tid >> 4;           // batch index

    float xi = 0.0f, wi = 0.0f;
    if (sub < NQ) {
        xi = x[b * NQ + sub];
        wi = __ldg(weight + sub);
    }

    // z = cp * (cw - sw*sp)
    float a  = PI_F * xi;
    float z  = __cosf(a) * (__cosf(wi) - __sinf(wi) * __sinf(a));

    // Scan input: lane 0 and padding lanes contribute identity.
    float v = (sub == 0u || sub >= NQ) ? 1.0f : z;

    // 4-step inclusive product scan over 16-lane groups: I_j = z_1..z_j.
    float I = v;
#pragma unroll
    for (int d = 1; d < 16; d <<= 1) {
        float t = __shfl_up_sync(0xffffffffu, I, d, 16);
        if (sub >= (unsigned)d) I *= t;
    }

    float z0  = __shfl_sync(0xffffffffu, z, 0, 16);    // z_0
    float s13 = __shfl_sync(0xffffffffu, I, 13, 16);   // z_1..z_13

    if (sub < NQ) {
        float o = z0 * I;                  // <Z_j> = z_0 * z_1..z_j
        if (sub == 0u) o = s13;            // <Z_0> = z_1..z_13
        out[b * NQ + sub] = o;
    }
}

extern "C" void kernel_launch(void* const* d_in, const int* in_sizes, int n_in,
                              void* d_out, int out_size)
{
    const float* x      = (const float*)d_in[0];   // [256, 14]
    const float* weight = (const float*)d_in[1];   // [1, 14]
    float* out          = (float*)d_out;           // [256, 14]

    // Measured-best shape: 256 batches x 16 lanes = 4096 threads, 32 x 128.
    quantum_layer_kernel<<<32, 128>>>(x, weight, out);
}

// round 9
// speedup vs baseline: 1.2372x; 1.0064x over previous
#include <cuda_runtime.h>

// QuantumLayer_9483287790225 — analytic closed form (R0 derivation).
//
// The circuit's single-qubit gates all precede the CNOT ring, so the
// pre-ring state is a product state with per-wire
//   z_i = cos(pi*x_i) * ( cos(w_i) - sin(w_i)*sin(pi*x_i) )
// and the ring conjugates Z_j into prefix products:
//   <Z_0> = z_1*...*z_13 ;  <Z_j> = z_0*...*z_j  (j>=1)
//
// R7 (final): measured-best shape 32 CTAs x 128 threads, 16 lanes per
// batch, lane = wire. Loads are clamped (lanes 14/15 reread wire 13,
// in-bounds) instead of predicated; the scan multiply uses a selected
// operand (FSEL + FMUL) instead of a predicated FMUL. Kernel is at the
// launch-overhead floor: all pipes ~0%, issue <3%, body <10% of time.

#define NQ 14
#define BATCH 256
#define PI_F 3.14159265358979323846f

__global__ void __launch_bounds__(128, 1)
quantum_layer_kernel(const float* __restrict__ x,
                     const float* __restrict__ weight,
                     float* __restrict__ out)
{
    const unsigned tid = blockIdx.x * blockDim.x + threadIdx.x;
    const unsigned sub = tid & 15u;          // wire index within 16-lane group
    const unsigned b   = tid >> 4;           // batch index

    // Clamped loads: padding lanes (14,15) reread wire 13 — in-bounds,
    // coalesced, no divergent predication on the LDG.
    const unsigned w = (sub < NQ) ? sub : (NQ - 1u);
    float xi = x[b * NQ + w];
    float wi = __ldg(weight + w);

    // z = cp * (cw - sw*sp)
    float a = PI_F * xi;
    float z = __cosf(a) * (__cosf(wi) - __sinf(wi) * __sinf(a));

    // Scan input: lane 0 and padding lanes contribute identity.
    float I = (sub == 0u || sub >= NQ) ? 1.0f : z;

    // 4-step inclusive product scan over 16-lane groups: I_j = z_1..z_j.
    // Select-operand form: unconditional FMUL fed by FSEL.
#pragma unroll
    for (int d = 1; d < 16; d <<= 1) {
        float t = __shfl_up_sync(0xffffffffu, I, d, 16);
        I *= (sub >= (unsigned)d) ? t : 1.0f;
    }

    float z0  = __shfl_sync(0xffffffffu, z, 0, 16);    // z_0
    float s13 = __shfl_sync(0xffffffffu, I, 13, 16);   // z_1..z_13

    if (sub < NQ) {
        float o = z0 * I;                  // <Z_j> = z_0 * z_1..z_j
        if (sub == 0u) o = s13;            // <Z_0> = z_1..z_13
        out[b * NQ + sub] = o;
    }
}

extern "C" void kernel_launch(void* const* d_in, const int* in_sizes, int n_in,
                              void* d_out, int out_size)
{
    const float* x      = (const float*)d_in[0];   // [256, 14]
    const float* weight = (const float*)d_in[1];   // [1, 14]
    float* out          = (float*)d_out;           // [256, 14]

    // Measured-best shape: 256 batches x 16 lanes = 4096 threads, 32 x 128.
    quantum_layer_kernel<<<32, 128>>>(x, weight, out);
}